// round 2
// baseline (speedup 1.0000x reference)
#include <cuda_runtime.h>
#include <math.h>

#define NTOK  4096
#define HID   1024
#define INTER 2048
#define NEXP  8
#define TOPK  2
#define NROWS (NTOK*TOPK)

// ---------------- scratch (static device globals; no allocation) ----------------
__device__ int   g_cnt[NEXP];
__device__ int   g_off[NEXP];
__device__ int   g_cursor[NEXP];
__device__ float g_psum[NEXP];
__device__ int   g_slot_e[NROWS];    // (token,slot) -> expert id
__device__ float g_slot_w[NROWS];    // (token,slot) -> normalized weight
__device__ int   g_rowidx[NROWS];    // (token,slot) -> compact row
__device__ int   g_row_tok[NROWS];   // compact row -> token
__device__ float g_h[NROWS * INTER]; // 64 MB intermediate (post-GELU)
__device__ float g_y[NROWS * HID];   // 32 MB per-row down-proj output

// ---------------- reset (graph-replay safe) ----------------
__global__ void k_reset() {
    int i = threadIdx.x;
    if (i < NEXP) { g_cnt[i] = 0; g_psum[i] = 0.f; }
}

// ---------------- router: logits, softmax, top2, weights, counts ----------------
__global__ __launch_bounds__(256) void k_router(const float* __restrict__ x,
                                                const float* __restrict__ rw) {
    int warp = (blockIdx.x * blockDim.x + threadIdx.x) >> 5;
    int lane = threadIdx.x & 31;
    if (warp >= NTOK) return;

    const float* xr = x + (size_t)warp * HID;
    float xv[HID / 32];
#pragma unroll
    for (int i = 0; i < HID / 32; i++) xv[i] = xr[lane + i * 32];

    float logit[NEXP];
#pragma unroll
    for (int e = 0; e < NEXP; e++) {
        const float* w = rw + (size_t)e * HID;
        float s = 0.f;
#pragma unroll
        for (int i = 0; i < HID / 32; i++) s += xv[i] * w[lane + i * 32];
#pragma unroll
        for (int o = 16; o > 0; o >>= 1) s += __shfl_xor_sync(0xffffffffu, s, o);
        logit[e] = s;
    }
    // softmax (all lanes redundantly)
    float mx = logit[0];
#pragma unroll
    for (int e = 1; e < NEXP; e++) mx = fmaxf(mx, logit[e]);
    float p[NEXP]; float se = 0.f;
#pragma unroll
    for (int e = 0; e < NEXP; e++) { p[e] = expf(logit[e] - mx); se += p[e]; }
    float inv = 1.f / se;
#pragma unroll
    for (int e = 0; e < NEXP; e++) p[e] *= inv;

    // top-2, first-index wins ties (matches jax top_k)
    int e0 = 0;
#pragma unroll
    for (int e = 1; e < NEXP; e++) if (p[e] > p[e0]) e0 = e;
    int e1 = -1;
#pragma unroll
    for (int e = 0; e < NEXP; e++) {
        if (e == e0) continue;
        if (e1 < 0 || p[e] > p[e1]) e1 = e;
    }
    float w0 = p[e0], w1 = p[e1];
    float ws = 1.f / (w0 + w1);
    w0 *= ws; w1 *= ws;

    if (lane == 0) {
        g_slot_e[warp * 2]     = e0;
        g_slot_e[warp * 2 + 1] = e1;
        g_slot_w[warp * 2]     = w0;
        g_slot_w[warp * 2 + 1] = w1;
        atomicAdd(&g_cnt[e0], 1);
        atomicAdd(&g_cnt[e1], 1);
    }
    if (lane < NEXP) atomicAdd(&g_psum[lane], p[lane]);
}

// ---------------- prefix offsets + aux loss ----------------
__global__ void k_offsets(float* __restrict__ out, int write_aux) {
    if (threadIdx.x == 0) {
        int acc = 0;
        float aux = 0.f;
        for (int e = 0; e < NEXP; e++) {
            g_off[e] = acc; g_cursor[e] = acc; acc += g_cnt[e];
            float f = (float)g_cnt[e] / (float)(NTOK * TOPK);
            float P = g_psum[e] / (float)NTOK;
            aux += f * P;
        }
        if (write_aux) out[(size_t)NTOK * HID] = aux * (float)NEXP;
    }
}

// ---------------- scatter tokens into compact per-expert segments ----------------
__global__ void k_scatter() {
    int i = blockIdx.x * blockDim.x + threadIdx.x;
    if (i >= NROWS) return;
    int e = g_slot_e[i];
    int pos = atomicAdd(&g_cursor[e], 1);
    g_rowidx[i] = pos;
    g_row_tok[pos] = i >> 1;
}

// ---------------- up-proj GEMM (gathered rows) + exact GELU ----------------
// C[r, f] = gelu( sum_h X[tok(r), h] * up_w[e, h, f] )
__global__ __launch_bounds__(256, 2) void k_up(const float* __restrict__ x,
                                               const float* __restrict__ up_w) {
    const int e = blockIdx.z;
    const int cnt = g_cnt[e];
    const int m0 = blockIdx.y * 128;
    if (m0 >= cnt) return;
    const int off = g_off[e];
    const int n0 = blockIdx.x * 128;
    const float* W = up_w + (size_t)e * HID * INTER;

    __shared__ float As[16][128];
    __shared__ float Bs[16][128];

    const int tid = threadIdx.x;
    const int tx = tid & 15, ty = tid >> 4;

    const int arow = tid & 127;
    const int ak0 = tid >> 7;        // 0..1
    const int ak1 = ak0 + 2;         // 2..3
    const float* ap = x + (size_t)g_row_tok[off + min(m0 + arow, cnt - 1)] * HID;

    const int bk0 = tid >> 5, bn0 = tid & 31, bk1 = bk0 + 8;

    float acc[8][8];
#pragma unroll
    for (int i = 0; i < 8; i++)
#pragma unroll
        for (int j = 0; j < 8; j++) acc[i][j] = 0.f;

    for (int k0 = 0; k0 < HID; k0 += 16) {
        float4 av0 = *(const float4*)(ap + k0 + ak0 * 4);
        float4 av1 = *(const float4*)(ap + k0 + ak1 * 4);
        float4 bv0 = *(const float4*)(W + (size_t)(k0 + bk0) * INTER + n0 + bn0 * 4);
        float4 bv1 = *(const float4*)(W + (size_t)(k0 + bk1) * INTER + n0 + bn0 * 4);
        __syncthreads();
        As[ak0 * 4 + 0][arow] = av0.x; As[ak0 * 4 + 1][arow] = av0.y;
        As[ak0 * 4 + 2][arow] = av0.z; As[ak0 * 4 + 3][arow] = av0.w;
        As[ak1 * 4 + 0][arow] = av1.x; As[ak1 * 4 + 1][arow] = av1.y;
        As[ak1 * 4 + 2][arow] = av1.z; As[ak1 * 4 + 3][arow] = av1.w;
        *(float4*)&Bs[bk0][bn0 * 4] = bv0;
        *(float4*)&Bs[bk1][bn0 * 4] = bv1;
        __syncthreads();
#pragma unroll
        for (int k = 0; k < 16; k++) {
            float4 a0 = *(const float4*)&As[k][ty * 8];
            float4 a1 = *(const float4*)&As[k][ty * 8 + 4];
            float4 b0 = *(const float4*)&Bs[k][tx * 8];
            float4 b1 = *(const float4*)&Bs[k][tx * 8 + 4];
            float a[8] = {a0.x, a0.y, a0.z, a0.w, a1.x, a1.y, a1.z, a1.w};
            float b[8] = {b0.x, b0.y, b0.z, b0.w, b1.x, b1.y, b1.z, b1.w};
#pragma unroll
            for (int i = 0; i < 8; i++)
#pragma unroll
                for (int j = 0; j < 8; j++) acc[i][j] += a[i] * b[j];
        }
    }
#pragma unroll
    for (int i = 0; i < 8; i++) {
        int r = m0 + ty * 8 + i;
        if (r < cnt) {
            float* dst = g_h + (size_t)(off + r) * INTER + n0 + tx * 8;
#pragma unroll
            for (int j = 0; j < 8; j++) {
                float v = acc[i][j];
                v = 0.5f * v * (1.f + erff(v * 0.70710678118654752f));
                dst[j] = v;
            }
        }
    }
}

// ---------------- down-proj GEMM ----------------
// Y[r, h] = sum_f H[r, f] * down_w[e, f, h]
__global__ __launch_bounds__(256, 2) void k_down(const float* __restrict__ dw) {
    const int e = blockIdx.z;
    const int cnt = g_cnt[e];
    const int m0 = blockIdx.y * 128;
    if (m0 >= cnt) return;
    const int off = g_off[e];
    const int n0 = blockIdx.x * 128;
    const float* W = dw + (size_t)e * INTER * HID;

    __shared__ float As[16][128];
    __shared__ float Bs[16][128];

    const int tid = threadIdx.x;
    const int tx = tid & 15, ty = tid >> 4;

    const int arow = tid & 127;
    const int ak0 = tid >> 7;
    const int ak1 = ak0 + 2;
    const float* ap = g_h + (size_t)(off + min(m0 + arow, cnt - 1)) * INTER;

    const int bk0 = tid >> 5, bn0 = tid & 31, bk1 = bk0 + 8;

    float acc[8][8];
#pragma unroll
    for (int i = 0; i < 8; i++)
#pragma unroll
        for (int j = 0; j < 8; j++) acc[i][j] = 0.f;

    for (int k0 = 0; k0 < INTER; k0 += 16) {
        float4 av0 = *(const float4*)(ap + k0 + ak0 * 4);
        float4 av1 = *(const float4*)(ap + k0 + ak1 * 4);
        float4 bv0 = *(const float4*)(W + (size_t)(k0 + bk0) * HID + n0 + bn0 * 4);
        float4 bv1 = *(const float4*)(W + (size_t)(k0 + bk1) * HID + n0 + bn0 * 4);
        __syncthreads();
        As[ak0 * 4 + 0][arow] = av0.x; As[ak0 * 4 + 1][arow] = av0.y;
        As[ak0 * 4 + 2][arow] = av0.z; As[ak0 * 4 + 3][arow] = av0.w;
        As[ak1 * 4 + 0][arow] = av1.x; As[ak1 * 4 + 1][arow] = av1.y;
        As[ak1 * 4 + 2][arow] = av1.z; As[ak1 * 4 + 3][arow] = av1.w;
        *(float4*)&Bs[bk0][bn0 * 4] = bv0;
        *(float4*)&Bs[bk1][bn0 * 4] = bv1;
        __syncthreads();
#pragma unroll
        for (int k = 0; k < 16; k++) {
            float4 a0 = *(const float4*)&As[k][ty * 8];
            float4 a1 = *(const float4*)&As[k][ty * 8 + 4];
            float4 b0 = *(const float4*)&Bs[k][tx * 8];
            float4 b1 = *(const float4*)&Bs[k][tx * 8 + 4];
            float a[8] = {a0.x, a0.y, a0.z, a0.w, a1.x, a1.y, a1.z, a1.w};
            float b[8] = {b0.x, b0.y, b0.z, b0.w, b1.x, b1.y, b1.z, b1.w};
#pragma unroll
            for (int i = 0; i < 8; i++)
#pragma unroll
                for (int j = 0; j < 8; j++) acc[i][j] += a[i] * b[j];
        }
    }
#pragma unroll
    for (int i = 0; i < 8; i++) {
        int r = m0 + ty * 8 + i;
        if (r < cnt) {
            float* dst = g_y + (size_t)(off + r) * HID + n0 + tx * 8;
#pragma unroll
            for (int j = 0; j < 8; j++) dst[j] = acc[i][j];
        }
    }
}

// ---------------- weighted combine (deterministic gather) ----------------
__global__ void k_combine(float* __restrict__ out) {
    int i = blockIdx.x * blockDim.x + threadIdx.x;   // over NTOK*HID/4
    int n = i >> 8;                                   // HID/4 = 256 float4/token
    int c = i & 255;
    int r0 = g_rowidx[2 * n], r1 = g_rowidx[2 * n + 1];
    float w0 = g_slot_w[2 * n], w1 = g_slot_w[2 * n + 1];
    const float4* y4 = (const float4*)g_y;
    float4 y0 = y4[(size_t)r0 * 256 + c];
    float4 y1 = y4[(size_t)r1 * 256 + c];
    float4 o;
    o.x = w0 * y0.x + w1 * y1.x;
    o.y = w0 * y0.y + w1 * y1.y;
    o.z = w0 * y0.z + w1 * y1.z;
    o.w = w0 * y0.w + w1 * y1.w;
    ((float4*)out)[i] = o;
}

// ---------------- launch ----------------
extern "C" void kernel_launch(void* const* d_in, const int* in_sizes, int n_in,
                              void* d_out, int out_size) {
    const float* x  = (const float*)d_in[0];
    const float* rw = (const float*)d_in[1];
    const float* up = (const float*)d_in[2];
    const float* dw = (const float*)d_in[3];
    float* out = (float*)d_out;

    k_reset<<<1, 32>>>();
    k_router<<<NTOK / 8, 256>>>(x, rw);
    k_offsets<<<1, 32>>>(out, out_size > NTOK * HID ? 1 : 0);
    k_scatter<<<(NROWS + 255) / 256, 256>>>();

    dim3 gu(INTER / 128, NTOK / 128, NEXP);
    k_up<<<gu, 256>>>(x, up);

    dim3 gd(HID / 128, NTOK / 128, NEXP);
    k_down<<<gd, 256>>>(dw);

    k_combine<<<(NTOK * HID / 4) / 256, 256>>>(out);
}